// round 3
// baseline (speedup 1.0000x reference)
#include <cuda_runtime.h>
#include <cuda_fp16.h>

// Problem: B=128, H=64, D=64 (n=m=D)
// Inputs (metadata order):
//  0: query  [128,64,64,64] f32
//  1: key    [128,64,64,64] f32
//  2: value  [128,64,64,64] f32
//  3: memory_key   [64,64,64] f32
//  4: memory_norm  [64] f32
//  5: memory_value [64,64,64] f32
//  6: compression_rate [64] f32
// Output (flat f32 concat):
//  memory_output [128,64,64,64] @ 0
//  scores        [128,64,64,64] @ 33554432
//  new_memory_key  [64,64]      @ 67108864
//  new_memory_norm [64]         @ 67112960

typedef unsigned long long u64t;

#define OFF_SCORES 33554432u
#define OFF_MKEY   67108864u
#define OFF_MNORM  67112960u

// ---------------- device scratch (no allocation allowed) ----------------
__device__ float g_sumK[4096];          // sum over (b,h) of key[n*64+d]
__device__ float g_sumV[4096];          // sum over (b,h) of value[n*64+d]
__device__ float g_P[64];               // sum over (b,h,d) of (sum_n f16(k)[n,d]) * f16(v)[m,d]
__device__ float g_mk16f[64 * 64 * 64]; // fp16-rounded memory_key as f32, layout [h][n][m]
__device__ float g_mvT[64 * 64 * 64];   // memory_value transposed, layout [h][m][n]

// ---------------- packed f32x2 helpers (sm_100+) ----------------
__device__ __forceinline__ u64t pk2(float x, float y) {
    u64t r;
    asm("mov.b64 %0, {%1, %2};" : "=l"(r) : "f"(x), "f"(y));
    return r;
}
__device__ __forceinline__ u64t dup2(float x) {
    u64t r;
    asm("mov.b64 %0, {%1, %1};" : "=l"(r) : "f"(x));
    return r;
}
__device__ __forceinline__ float2 upk2(u64t v) {
    float2 r;
    asm("mov.b64 {%0, %1}, %2;" : "=f"(r.x), "=f"(r.y) : "l"(v));
    return r;
}
#define FFMA2(acc, aa, bb) \
    asm("fma.rn.f32x2 %0, %1, %2, %0;" : "+l"(acc) : "l"(aa), "l"(bb))

__device__ __forceinline__ float r16(float x) {
    return __half2float(__float2half_rn(x));
}

// ---------------- kernel 0: zero accumulators ----------------
__global__ void k_zero() {
    int t = blockIdx.x * blockDim.x + threadIdx.x;
    if (t < 4096) { g_sumK[t] = 0.f; g_sumV[t] = 0.f; }
    if (t < 64) g_P[t] = 0.f;
}

// ---------------- kernel 1: update-path statistics ----------------
// grid 512: b = bid/4, h-range = (bid%4)*16..+16. 256 threads.
__global__ void __launch_bounds__(256) k_update(const float* __restrict__ key,
                                                const float* __restrict__ value) {
    __shared__ float red[256];
    __shared__ float sk[64];
    __shared__ float Pm[64];

    int t = threadIdx.x;
    int b = blockIdx.x >> 2;
    int h0 = (blockIdx.x & 3) << 4;

    if (t < 64) Pm[t] = 0.f;
    float accK[16], accV[16];
#pragma unroll
    for (int i = 0; i < 16; i++) { accK[i] = 0.f; accV[i] = 0.f; }
    __syncthreads();

    for (int hh = 0; hh < 16; hh++) {
        int h = h0 + hh;
        const float* kb = key + (((unsigned)(b * 64 + h)) << 12);
        const float* vb = value + (((unsigned)(b * 64 + h)) << 12);
        float pk = 0.f;
        float v16r[16];
#pragma unroll
        for (int i = 0; i < 16; i++) {
            int e = t + (i << 8);            // e = n*64+d; n = 4i + (t>>6), d = t&63
            float kv = kb[e];
            float vv = vb[e];
            accK[i] += kv;
            accV[i] += vv;
            pk += r16(kv);
            v16r[i] = r16(vv);
        }
        red[t] = pk;
        __syncthreads();
        if (t < 64) sk[t] = red[t] + red[t + 64] + red[t + 128] + red[t + 192];
        __syncthreads();
        float skd = sk[t & 63];              // sum_n f16(k)[n, d=t&63]
        int mb0 = t >> 6;
#pragma unroll
        for (int i = 0; i < 16; i++) {
            float c = skd * v16r[i];         // contribution to P[m = 4i+mb0] from this d
            c += __shfl_xor_sync(0xffffffffu, c, 16);
            c += __shfl_xor_sync(0xffffffffu, c, 8);
            c += __shfl_xor_sync(0xffffffffu, c, 4);
            c += __shfl_xor_sync(0xffffffffu, c, 2);
            c += __shfl_xor_sync(0xffffffffu, c, 1);
            if ((t & 31) == 0) atomicAdd(&Pm[mb0 + (i << 2)], c);
        }
        __syncthreads();
    }
#pragma unroll
    for (int i = 0; i < 16; i++) {
        int e = t + (i << 8);
        atomicAdd(&g_sumK[e], accK[i]);
        atomicAdd(&g_sumV[e], accV[i]);
    }
    if (t < 64) atomicAdd(&g_P[t], Pm[t]);
}

// ---------------- kernel 2: finalize small outputs (1 CTA, 64 thr) ----------------
__global__ void k_stats(const float* __restrict__ memory_norm,
                        const float* __restrict__ comp,
                        float* __restrict__ out_key,
                        float* __restrict__ out_norm) {
    __shared__ float nn_s[64];
    __shared__ float mean_nn;
    int t = threadIdx.x;  // 0..63

    float s = 0.f;
#pragma unroll 8
    for (int d = 0; d < 64; d++) {
        float kb = g_sumK[t * 64 + d] * (1.f / 8192.f);
        s += kb * kb;
    }
    float nn = memory_norm[t] + sqrtf(s);
    nn_s[t] = nn;
    __syncthreads();
    if (t == 0) {
        float m = 0.f;
        for (int i = 0; i < 64; i++) m += nn_s[i];
        mean_nn = m * (1.f / 64.f);
    }
    __syncthreads();
    float factor = (mean_nn > 0.9f) ? comp[t] : 1.0f;
    out_norm[t] = nn * factor;
    float mbind = g_P[t] * (1.f / 524288.f);        // /(B*H*N)
    float scale = mbind * factor * (1.f / 8192.f);  // mean_value = sumV/(B*H)
#pragma unroll 8
    for (int d = 0; d < 64; d++)
        out_key[t * 64 + d] = scale * g_sumV[t * 64 + d];
}

// ---------------- kernel 3: prep retrieve operands (grid 64, 256 thr) ----------------
__global__ void __launch_bounds__(256) k_prep(const float* __restrict__ mk,
                                              const float* __restrict__ mv) {
    __shared__ float T[64 * 65];
    int h = blockIdx.x, t = threadIdx.x;
    const float* mks = mk + ((unsigned)h << 12);
    const float* mvs = mv + ((unsigned)h << 12);
    float* dk = g_mk16f + ((unsigned)h << 12);
    float* dv = g_mvT + ((unsigned)h << 12);
    for (int i = t; i < 4096; i += 256) {
        dk[i] = r16(mks[i]);
        float v = mvs[i];               // mv[n][m], n=i>>6, m=i&63
        T[(i & 63) * 65 + (i >> 6)] = v;
    }
    __syncthreads();
    for (int i = t; i < 4096; i += 256) // dv[m][n] = mv[n][m]
        dv[i] = T[(i >> 6) * 65 + (i & 63)];
}

// ---------------- kernel 4: retrieve (two fused 64^3 GEMMs per tile) ----------------
// C[row][col] = sum_k A[k][row] * Bt[k][col]; per-thread 8x8 tile via f32x2.
__device__ __forceinline__ void gemm64(const float* __restrict__ A,
                                       const float* __restrict__ Bt,
                                       u64t acc[8][4], int ty, int tx) {
    const float4* A4 = (const float4*)A;
    const float4* B4 = (const float4*)Bt;
#pragma unroll 4
    for (int k = 0; k < 64; k++) {
        float4 a0 = A4[k * 16 + ty * 2];
        float4 a1 = A4[k * 16 + ty * 2 + 1];
        float4 b0 = B4[k * 16 + tx * 2];
        float4 b1 = B4[k * 16 + tx * 2 + 1];
        u64t bb0 = pk2(b0.x, b0.y);
        u64t bb1 = pk2(b0.z, b0.w);
        u64t bb2 = pk2(b1.x, b1.y);
        u64t bb3 = pk2(b1.z, b1.w);
        float av[8] = {a0.x, a0.y, a0.z, a0.w, a1.x, a1.y, a1.z, a1.w};
#pragma unroll
        for (int im = 0; im < 8; im++) {
            u64t ad = dup2(av[im]);
            FFMA2(acc[im][0], ad, bb0);
            FFMA2(acc[im][1], ad, bb1);
            FFMA2(acc[im][2], ad, bb2);
            FFMA2(acc[im][3], ad, bb3);
        }
    }
}

// grid 4096: bid = h*64 + bg. 128 threads = 2 tiles (b = bg*2 + tile) sharing h.
// Dynamic smem: 3 * 4096 floats = 48 KB (fits default limit, no opt-in needed).
__global__ void __launch_bounds__(128) k_retrieve(const float* __restrict__ q,
                                                  const float* __restrict__ memory_norm,
                                                  float* __restrict__ scores_out,
                                                  float* __restrict__ out_out) {
    extern __shared__ float smem[];
    float* As = smem;  // 4096 f32: mk16f[h], then mvT[h]
    int h = blockIdx.x >> 6;
    int bg = blockIdx.x & 63;
    int t = threadIdx.x;
    int tile = t >> 6;             // 0..1
    int b = (bg << 1) | tile;
    int lt = t & 63;
    int tx = lt & 7;               // col block (d)
    int ty = lt >> 3;              // row block (m / n)
    float* myB = smem + 4096 * (1 + tile);
    unsigned base = ((unsigned)(b * 64 + h)) << 12;

    // load A = mk16f[h] (cooperative, 128 threads)
    {
        const float4* src = (const float4*)(g_mk16f + ((unsigned)h << 12));
        float4* dst = (float4*)As;
        for (int i = t; i < 1024; i += 128) dst[i] = src[i];
    }
    // load this tile's q, fp16-rounded (values kept in f32)
    {
        const float4* qs = (const float4*)(q + base);
        float4* d4 = (float4*)myB;
        for (int i = lt; i < 1024; i += 64) {
            float4 v = qs[i];
            float2 f0 = __half22float2(__floats2half2_rn(v.x, v.y));
            float2 f1 = __half22float2(__floats2half2_rn(v.z, v.w));
            v.x = f0.x; v.y = f0.y; v.z = f1.x; v.w = f1.y;
            d4[i] = v;
        }
    }
    __syncthreads();

    // ---- GEMM1: raw[m][d] = sum_n mk16[n][m] * q16[n][d] ----
    u64t acc[8][4];
#pragma unroll
    for (int i = 0; i < 8; i++)
#pragma unroll
        for (int j = 0; j < 4; j++) acc[i][j] = 0ull;
    gemm64(As, myB, acc, ty, tx);
    __syncthreads();  // all tiles done reading As / myB(q)

    // reload As = mvT[h]
    {
        const float4* src = (const float4*)(g_mvT + ((unsigned)h << 12));
        float4* dst = (float4*)As;
        for (int i = t; i < 1024; i += 128) dst[i] = src[i];
    }
    // epilogue 1: scores = f16round(raw) / (norm[d]+1e-6) -> gmem + smem
    {
        float inv[8];
#pragma unroll
        for (int j = 0; j < 8; j++) inv[j] = 1.0f / (memory_norm[tx * 8 + j] + 1e-6f);
        float* so = scores_out + base;
#pragma unroll
        for (int im = 0; im < 8; im++) {
            int m = ty * 8 + im;
            float v[8];
#pragma unroll
            for (int j = 0; j < 4; j++) {
                float2 p = upk2(acc[im][j]);
                v[2 * j] = p.x; v[2 * j + 1] = p.y;
            }
#pragma unroll
            for (int j = 0; j < 8; j++) v[j] = r16(v[j]) * inv[j];
            float4* sm4 = (float4*)(myB + m * 64 + tx * 8);
            sm4[0] = make_float4(v[0], v[1], v[2], v[3]);
            sm4[1] = make_float4(v[4], v[5], v[6], v[7]);
            float4* so4 = (float4*)(so + m * 64 + tx * 8);
            so4[0] = make_float4(v[0], v[1], v[2], v[3]);
            so4[1] = make_float4(v[4], v[5], v[6], v[7]);
#pragma unroll
            for (int j = 0; j < 4; j++) acc[im][j] = 0ull;
        }
    }
    __syncthreads();

    // ---- GEMM2: out[n][d] = sum_m mvT[m][n] * scores[m][d] ----
    gemm64(As, myB, acc, ty, tx);

    // epilogue 2
    {
        float* oo = out_out + base;
#pragma unroll
        for (int im = 0; im < 8; im++) {
            int n = ty * 8 + im;
            float v[8];
#pragma unroll
            for (int j = 0; j < 4; j++) {
                float2 p = upk2(acc[im][j]);
                v[2 * j] = p.x; v[2 * j + 1] = p.y;
            }
            float4* oo4 = (float4*)(oo + n * 64 + tx * 8);
            oo4[0] = make_float4(v[0], v[1], v[2], v[3]);
            oo4[1] = make_float4(v[4], v[5], v[6], v[7]);
        }
    }
}

extern "C" void kernel_launch(void* const* d_in, const int* in_sizes, int n_in,
                              void* d_out, int out_size) {
    const float* query   = (const float*)d_in[0];
    const float* key     = (const float*)d_in[1];
    const float* value   = (const float*)d_in[2];
    const float* mkey    = (const float*)d_in[3];
    const float* mnorm   = (const float*)d_in[4];
    const float* mvalue  = (const float*)d_in[5];
    const float* comp    = (const float*)d_in[6];
    float* out = (float*)d_out;

    k_zero<<<16, 256>>>();
    k_update<<<512, 256>>>(key, value);
    k_stats<<<1, 64>>>(mnorm, comp, out + OFF_MKEY, out + OFF_MNORM);
    k_prep<<<64, 256>>>(mkey, mvalue);
    k_retrieve<<<4096, 128, 3 * 4096 * sizeof(float)>>>(
        query, mnorm, out + OFF_SCORES, out);
}

// round 5
// speedup vs baseline: 2.0830x; 2.0830x over previous
#include <cuda_runtime.h>
#include <cuda_fp16.h>

// Problem: B=128, H=64, D=64 (n=m=D)
// Inputs: 0 query, 1 key, 2 value [128,64,64,64] f32; 3 memory_key [64,64,64];
//         4 memory_norm [64]; 5 memory_value [64,64,64]; 6 compression_rate [64]
// Output f32 concat: memory_output @0, scores @33554432, new_memory_key @67108864,
//                    new_memory_norm @67112960

#define OFF_SCORES 33554432u
#define OFF_MKEY   67108864u
#define OFF_MNORM  67112960u

__device__ float g_sumK[4096];   // sum over (b,h) of key[n*64+d]
__device__ float g_sumV[4096];   // sum over (b,h) of value[n*64+d]
__device__ float g_P[64];        // sum over (b,h,d) of (sum_n f16k[n,d]) * f16v[m,d]

__device__ __forceinline__ float r16(float x) { return __half2float(__float2half_rn(x)); }
__device__ __forceinline__ unsigned sptr(const void* p) {
    return (unsigned)__cvta_generic_to_shared(p);
}

// ---------------- kernel 0: zero accumulators ----------------
__global__ void k_zero() {
    int t = blockIdx.x * blockDim.x + threadIdx.x;
    if (t < 4096) { g_sumK[t] = 0.f; g_sumV[t] = 0.f; }
    if (t < 64) g_P[t] = 0.f;
}

// ---------------- kernel 1: update-path statistics ----------------
// grid 512: b = bid/4, h-range = (bid%4)*16..+16. 256 threads.
__global__ void __launch_bounds__(256) k_update(const float* __restrict__ key,
                                                const float* __restrict__ value) {
    __shared__ float red[256];
    __shared__ float sk[64];
    __shared__ float Pm[64];

    int t = threadIdx.x;
    int b = blockIdx.x >> 2;
    int h0 = (blockIdx.x & 3) << 4;

    if (t < 64) Pm[t] = 0.f;
    float accK[16], accV[16], localP[16];
#pragma unroll
    for (int i = 0; i < 16; i++) { accK[i] = 0.f; accV[i] = 0.f; localP[i] = 0.f; }
    __syncthreads();

    for (int hh = 0; hh < 16; hh++) {
        int h = h0 + hh;
        const float* kb = key + (((unsigned)(b * 64 + h)) << 12);
        const float* vb = value + (((unsigned)(b * 64 + h)) << 12);
        float pk = 0.f;
        float v16r[16];
#pragma unroll
        for (int i = 0; i < 16; i++) {
            int e = t + (i << 8);            // e = n*64+d; n = (t>>6)+4i, d = t&63
            float kv = kb[e];
            float vv = vb[e];
            accK[i] += kv;
            accV[i] += vv;
            pk += r16(kv);
            v16r[i] = r16(vv);
        }
        red[t] = pk;
        __syncthreads();
        if (t < 64) sk[t] = red[t] + red[t + 64] + red[t + 128] + red[t + 192];
        __syncthreads();
        float skd = sk[t & 63];              // sum_n f16k[n, d]
#pragma unroll
        for (int i = 0; i < 16; i++) localP[i] += skd * v16r[i];
    }
    // single reduction at the end: sum localP over d (32 lanes of a warp share m)
    int mb0 = t >> 6;
#pragma unroll
    for (int i = 0; i < 16; i++) {
        float c = localP[i];
        c += __shfl_xor_sync(0xffffffffu, c, 16);
        c += __shfl_xor_sync(0xffffffffu, c, 8);
        c += __shfl_xor_sync(0xffffffffu, c, 4);
        c += __shfl_xor_sync(0xffffffffu, c, 2);
        c += __shfl_xor_sync(0xffffffffu, c, 1);
        if ((t & 31) == 0) atomicAdd(&Pm[mb0 + (i << 2)], c);
    }
    __syncthreads();
    if (t < 64) atomicAdd(&g_P[t], Pm[t]);
#pragma unroll
    for (int i = 0; i < 16; i++) {
        int e = t + (i << 8);
        atomicAdd(&g_sumK[e], accK[i]);
        atomicAdd(&g_sumV[e], accV[i]);
    }
}

// ---------------- kernel 2: finalize small outputs (1 CTA, 64 thr) ----------------
__global__ void k_stats(const float* __restrict__ memory_norm,
                        const float* __restrict__ comp,
                        float* __restrict__ out_key,
                        float* __restrict__ out_norm) {
    __shared__ float nn_s[64];
    __shared__ float mean_nn;
    int t = threadIdx.x;  // 0..63

    float s = 0.f;
#pragma unroll 8
    for (int d = 0; d < 64; d++) {
        float kb = g_sumK[t * 64 + d] * (1.f / 8192.f);
        s += kb * kb;
    }
    float nn = memory_norm[t] + sqrtf(s);
    nn_s[t] = nn;
    __syncthreads();
    if (t == 0) {
        float m = 0.f;
        for (int i = 0; i < 64; i++) m += nn_s[i];
        mean_nn = m * (1.f / 64.f);
    }
    __syncthreads();
    float factor = (mean_nn > 0.9f) ? comp[t] : 1.0f;
    out_norm[t] = nn * factor;
    float mbind = g_P[t] * (1.f / 524288.f);        // /(B*H*N)
    float scale = mbind * factor * (1.f / 8192.f);  // mean_value = sumV/(B*H)
#pragma unroll 8
    for (int d = 0; d < 64; d++)
        out_key[t * 64 + d] = scale * g_sumV[t * 64 + d];
}

// ---------------- kernel 3: retrieve via HMMA ----------------
// grid 512: h = bid>>3, bg = bid&7; each CTA does 16 b-values with 128 threads (4 warps).
// GEMM1: raw[m][d] = sum_n mkT[m][n] * q16[n][d]       (A = mkT [m][n], B = q16 [n][d] via ldmatrix.trans)
// GEMM2: out[n][d] = inv[d] * sum_m mv[n][m] * s16[m][d] (A = mv hi/lo [n][m], B = s16 [m][d] via ldmatrix.trans)
#define RP 72   // padded row length in halves (conflict-free ldmatrix)

__global__ void __launch_bounds__(128) k_retrieve(const float* __restrict__ q,
                                                  const float* __restrict__ mkey,
                                                  const float* __restrict__ mvalue,
                                                  const float* __restrict__ mnorm,
                                                  float* __restrict__ scores_out,
                                                  float* __restrict__ out_out) {
    __shared__ __half s_mkT[64 * RP];   // A1: [m][n]
    __shared__ __half s_mvhi[64 * RP];  // A2 hi: [n][m]
    __shared__ __half s_mvlo[64 * RP];  // A2 lo: [n][m]
    __shared__ __half s_q[64 * RP];     // B1: [n][d]
    __shared__ __half s_s[64 * RP];     // B2: [m][d]
    __shared__ float s_inv[64];

    int t = threadIdx.x, w = t >> 5, lane = t & 31, g = lane >> 2, tq = lane & 3;
    int h = blockIdx.x >> 3, bg = blockIdx.x & 7;

    if (t < 64) s_inv[t] = 1.0f / (mnorm[t] + 1e-6f);
    {
        const float* mk = mkey + ((unsigned)h << 12);
        const float* mv = mvalue + ((unsigned)h << 12);
        for (int i = t; i < 4096; i += 128) {
            int n = i >> 6, m = i & 63;
            s_mkT[m * RP + n] = __float2half_rn(mk[i]);
            float v = mv[i];
            __half hi = __float2half_rn(v);
            s_mvhi[n * RP + m] = hi;
            s_mvlo[n * RP + m] = __float2half_rn(v - __half2float(hi));
        }
    }
    __syncthreads();

    // preload A fragments (reused for all 16 b)
    int matv = lane >> 3, rr = lane & 7;
    int arow = w * 16 + rr + (matv & 1) * 8;
    int acolo = (matv >> 1) * 8;
    unsigned a1[4][4], ah[4][4], al[4][4];
#pragma unroll
    for (int ks = 0; ks < 4; ks++) {
        unsigned ad = sptr(&s_mkT[arow * RP + ks * 16 + acolo]);
        asm volatile("ldmatrix.sync.aligned.m8n8.x4.shared.b16 {%0,%1,%2,%3},[%4];"
                     : "=r"(a1[ks][0]), "=r"(a1[ks][1]), "=r"(a1[ks][2]), "=r"(a1[ks][3])
                     : "r"(ad));
        ad = sptr(&s_mvhi[arow * RP + ks * 16 + acolo]);
        asm volatile("ldmatrix.sync.aligned.m8n8.x4.shared.b16 {%0,%1,%2,%3},[%4];"
                     : "=r"(ah[ks][0]), "=r"(ah[ks][1]), "=r"(ah[ks][2]), "=r"(ah[ks][3])
                     : "r"(ad));
        ad = sptr(&s_mvlo[arow * RP + ks * 16 + acolo]);
        asm volatile("ldmatrix.sync.aligned.m8n8.x4.shared.b16 {%0,%1,%2,%3},[%4];"
                     : "=r"(al[ks][0]), "=r"(al[ks][1]), "=r"(al[ks][2]), "=r"(al[ks][3])
                     : "r"(ad));
    }
    int l16 = lane & 15;
    int brow = ((l16 >> 3) * 8 + (l16 & 7)) * RP;  // + ks*16*RP per k-step

    for (int j = 0; j < 16; j++) {
        int b = bg * 16 + j;
        unsigned base = ((unsigned)(b * 64 + h)) << 12;

        // load q -> s_q (f32 -> f16)
        {
            const float4* q4 = (const float4*)(q + base);
            for (int i = t; i < 1024; i += 128) {
                float4 v = q4[i];
                int n = i >> 4, d4 = (i & 15) << 2;
                *(__half2*)&s_q[n * RP + d4]     = __floats2half2_rn(v.x, v.y);
                *(__half2*)&s_q[n * RP + d4 + 2] = __floats2half2_rn(v.z, v.w);
            }
        }
        __syncthreads();

        // GEMM1 + scores epilogue
        float* sco = scores_out + base;
#pragma unroll
        for (int nt = 0; nt < 8; nt++) {
            float c0 = 0.f, c1 = 0.f, c2 = 0.f, c3 = 0.f;
#pragma unroll
            for (int ks = 0; ks < 4; ks++) {
                unsigned b0, b1;
                unsigned bad = sptr(&s_q[ks * 16 * RP + brow + nt * 8]);
                asm volatile("ldmatrix.sync.aligned.m8n8.x2.trans.shared.b16 {%0,%1},[%2];"
                             : "=r"(b0), "=r"(b1) : "r"(bad));
                asm volatile(
                    "mma.sync.aligned.m16n8k16.row.col.f32.f16.f16.f32 "
                    "{%0,%1,%2,%3},{%4,%5,%6,%7},{%8,%9},{%0,%1,%2,%3};"
                    : "+f"(c0), "+f"(c1), "+f"(c2), "+f"(c3)
                    : "r"(a1[ks][0]), "r"(a1[ks][1]), "r"(a1[ks][2]), "r"(a1[ks][3]),
                      "r"(b0), "r"(b1));
            }
            int m0 = w * 16 + g, d0 = nt * 8 + 2 * tq;
            __half h0 = __float2half_rn(c0), h1 = __float2half_rn(c1);
            __half h2 = __float2half_rn(c2), h3 = __float2half_rn(c3);
            *(__half2*)&s_s[m0 * RP + d0]       = __halves2half2(h0, h1);
            *(__half2*)&s_s[(m0 + 8) * RP + d0] = __halves2half2(h2, h3);
            float iv0 = s_inv[d0], iv1 = s_inv[d0 + 1];
            *(float2*)&sco[m0 * 64 + d0] =
                make_float2(__half2float(h0) * iv0, __half2float(h1) * iv1);
            *(float2*)&sco[(m0 + 8) * 64 + d0] =
                make_float2(__half2float(h2) * iv0, __half2float(h3) * iv1);
        }
        __syncthreads();

        // GEMM2 + output epilogue
        float* oo = out_out + base;
#pragma unroll
        for (int nt = 0; nt < 8; nt++) {
            float c0 = 0.f, c1 = 0.f, c2 = 0.f, c3 = 0.f;
#pragma unroll
            for (int ks = 0; ks < 4; ks++) {
                unsigned b0, b1;
                unsigned bad = sptr(&s_s[ks * 16 * RP + brow + nt * 8]);
                asm volatile("ldmatrix.sync.aligned.m8n8.x2.trans.shared.b16 {%0,%1},[%2];"
                             : "=r"(b0), "=r"(b1) : "r"(bad));
                asm volatile(
                    "mma.sync.aligned.m16n8k16.row.col.f32.f16.f16.f32 "
                    "{%0,%1,%2,%3},{%4,%5,%6,%7},{%8,%9},{%0,%1,%2,%3};"
                    : "+f"(c0), "+f"(c1), "+f"(c2), "+f"(c3)
                    : "r"(ah[ks][0]), "r"(ah[ks][1]), "r"(ah[ks][2]), "r"(ah[ks][3]),
                      "r"(b0), "r"(b1));
                asm volatile(
                    "mma.sync.aligned.m16n8k16.row.col.f32.f16.f16.f32 "
                    "{%0,%1,%2,%3},{%4,%5,%6,%7},{%8,%9},{%0,%1,%2,%3};"
                    : "+f"(c0), "+f"(c1), "+f"(c2), "+f"(c3)
                    : "r"(al[ks][0]), "r"(al[ks][1]), "r"(al[ks][2]), "r"(al[ks][3]),
                      "r"(b0), "r"(b1));
            }
            int n0 = w * 16 + g, d0 = nt * 8 + 2 * tq;
            float iv0 = s_inv[d0], iv1 = s_inv[d0 + 1];
            *(float2*)&oo[n0 * 64 + d0]       = make_float2(c0 * iv0, c1 * iv1);
            *(float2*)&oo[(n0 + 8) * 64 + d0] = make_float2(c2 * iv0, c3 * iv1);
        }
        // next iteration's q-load sync provides the s_s write/read fence
    }
}

extern "C" void kernel_launch(void* const* d_in, const int* in_sizes, int n_in,
                              void* d_out, int out_size) {
    const float* query  = (const float*)d_in[0];
    const float* key    = (const float*)d_in[1];
    const float* value  = (const float*)d_in[2];
    const float* mkey   = (const float*)d_in[3];
    const float* mnorm  = (const float*)d_in[4];
    const float* mvalue = (const float*)d_in[5];
    const float* comp   = (const float*)d_in[6];
    float* out = (float*)d_out;

    k_zero<<<16, 256>>>();
    k_update<<<512, 256>>>(key, value);
    k_stats<<<1, 64>>>(mnorm, comp, out + OFF_MKEY, out + OFF_MNORM);
    k_retrieve<<<512, 128>>>(query, mkey, mvalue, mnorm, out + OFF_SCORES, out);
}

// round 8
// speedup vs baseline: 2.2899x; 1.0993x over previous
#include <cuda_runtime.h>
#include <cuda_fp16.h>

// Problem: B=128, H=64, D=64 (n=m=D)
// Inputs: 0 query, 1 key, 2 value [128,64,64,64] f32; 3 memory_key [64,64,64];
//         4 memory_norm [64]; 5 memory_value [64,64,64]; 6 compression_rate [64]
// Output f32 concat: memory_output @0, scores @33554432, new_memory_key @67108864,
//                    new_memory_norm @67112960

#define OFF_SCORES 33554432u
#define OFF_MKEY   67108864u
#define OFF_MNORM  67112960u

typedef unsigned long long u64t;

__device__ float g_sumK[4096];   // sum over (b,h) of key[n*64+d]
__device__ float g_sumV[4096];   // sum over (b,h) of value[n*64+d]
__device__ float g_P[64];        // sum over (b,h,d) of (sum_n f16k[n,d]) * f16v[m,d]

__device__ __forceinline__ unsigned sptr(const void* p) {
    return (unsigned)__cvta_generic_to_shared(p);
}
__device__ __forceinline__ u64t pk2(float x, float y) {
    u64t r; asm("mov.b64 %0, {%1, %2};" : "=l"(r) : "f"(x), "f"(y)); return r;
}
__device__ __forceinline__ float2 upk2(u64t v) {
    float2 r; asm("mov.b64 {%0, %1}, %2;" : "=f"(r.x), "=f"(r.y) : "l"(v)); return r;
}
#define ADD2(acc, vv) asm("add.rn.f32x2 %0, %0, %1;" : "+l"(acc) : "l"(vv))
#define FFMA2(acc, aa, bb) asm("fma.rn.f32x2 %0, %1, %2, %0;" : "+l"(acc) : "l"(aa), "l"(bb))

// round both lanes of a packed f32x2 to fp16 and back (matches reference fp16 cast)
__device__ __forceinline__ u64t r16x2(u64t v) {
    float2 f = upk2(v);
    __half2 h = __floats2half2_rn(f.x, f.y);
    float2 g = __half22float2(h);
    return pk2(g.x, g.y);
}

// ---------------- kernel 0: zero accumulators ----------------
__global__ void k_zero() {
    int t = blockIdx.x * blockDim.x + threadIdx.x;
    if (t < 4096) { g_sumK[t] = 0.f; g_sumV[t] = 0.f; }
    if (t < 64) g_P[t] = 0.f;
}

// ---------------- kernel 1: update-path statistics (float2/packed) ----------------
// grid 512: b = bid/4, h-range = (bid%4)*16..+16. 256 threads.
// float2 element index f = n*32 + dp  (n = row 0..63, dp = d-pair 0..31)
// thread t handles f = t + 256*i, i<8  ->  dp = t&31, n = (t>>5) + 8i
__global__ void __launch_bounds__(256) k_update(const float* __restrict__ key,
                                                const float* __restrict__ value) {
    __shared__ float2 red2[256];
    __shared__ float2 sk2[32];
    __shared__ float Pm[64];

    int t = threadIdx.x;
    int dp = t & 31, n0 = t >> 5;
    int b = blockIdx.x >> 2;
    int h0 = (blockIdx.x & 3) << 4;

    if (t < 64) Pm[t] = 0.f;
    u64t accK[8], accV[8], lp2[8];
#pragma unroll
    for (int i = 0; i < 8; i++) { accK[i] = 0ull; accV[i] = 0ull; lp2[i] = 0ull; }
    __syncthreads();

    for (int hh = 0; hh < 16; hh++) {
        int h = h0 + hh;
        const u64t* kb = (const u64t*)(key + (((unsigned)(b * 64 + h)) << 12));
        const u64t* vb = (const u64t*)(value + (((unsigned)(b * 64 + h)) << 12));
        u64t pkacc = 0ull;
        u64t v16p[8];
#pragma unroll
        for (int i = 0; i < 8; i++) {
            int f = t + (i << 8);
            u64t kv = kb[f];
            u64t vv = vb[f];
            ADD2(accK[i], kv);
            ADD2(accV[i], vv);
            u64t k16 = r16x2(kv);
            ADD2(pkacc, k16);
            v16p[i] = r16x2(vv);
        }
        red2[t] = upk2(pkacc);
        __syncthreads();
        if (t < 32) {
            float2 s = red2[t];
            float2 a1 = red2[t + 32], a2 = red2[t + 64], a3 = red2[t + 96];
            float2 a4 = red2[t + 128], a5 = red2[t + 160], a6 = red2[t + 192], a7 = red2[t + 224];
            s.x += a1.x + a2.x + a3.x + a4.x + a5.x + a6.x + a7.x;
            s.y += a1.y + a2.y + a3.y + a4.y + a5.y + a6.y + a7.y;
            sk2[t] = s;                 // sk2[dp] = sum_n f16k[n, 2dp..2dp+1]
        }
        __syncthreads();
        float2 skf = sk2[dp];
        u64t skp = pk2(skf.x, skf.y);
#pragma unroll
        for (int i = 0; i < 8; i++) FFMA2(lp2[i], skp, v16p[i]);  // P[m=n0+8i] partial
        __syncthreads();  // protect sk2/red2 reuse next hh
    }

    // reduce localP over the 32 dp lanes of each warp (all share n0)
#pragma unroll
    for (int i = 0; i < 8; i++) {
        float2 l = upk2(lp2[i]);
        float c = l.x + l.y;
        c += __shfl_xor_sync(0xffffffffu, c, 16);
        c += __shfl_xor_sync(0xffffffffu, c, 8);
        c += __shfl_xor_sync(0xffffffffu, c, 4);
        c += __shfl_xor_sync(0xffffffffu, c, 2);
        c += __shfl_xor_sync(0xffffffffu, c, 1);
        if (dp == 0) atomicAdd(&Pm[n0 + (i << 3)], c);
    }
    __syncthreads();
    if (t < 64) atomicAdd(&g_P[t], Pm[t]);
#pragma unroll
    for (int i = 0; i < 8; i++) {
        int f = t + (i << 8);
        float2 a = upk2(accK[i]);
        float2 v = upk2(accV[i]);
        atomicAdd(&g_sumK[2 * f], a.x);
        atomicAdd(&g_sumK[2 * f + 1], a.y);
        atomicAdd(&g_sumV[2 * f], v.x);
        atomicAdd(&g_sumV[2 * f + 1], v.y);
    }
}

// ---------------- kernel 2: finalize small outputs (1 CTA, 64 thr) ----------------
__global__ void k_stats(const float* __restrict__ memory_norm,
                        const float* __restrict__ comp,
                        float* __restrict__ out_key,
                        float* __restrict__ out_norm) {
    __shared__ float nn_s[64];
    __shared__ float mean_nn;
    int t = threadIdx.x;  // 0..63

    float s = 0.f;
#pragma unroll 8
    for (int d = 0; d < 64; d++) {
        float kb = g_sumK[t * 64 + d] * (1.f / 8192.f);
        s += kb * kb;
    }
    float nn = memory_norm[t] + sqrtf(s);
    nn_s[t] = nn;
    __syncthreads();
    if (t == 0) {
        float m = 0.f;
        for (int i = 0; i < 64; i++) m += nn_s[i];
        mean_nn = m * (1.f / 64.f);
    }
    __syncthreads();
    float factor = (mean_nn > 0.9f) ? comp[t] : 1.0f;
    out_norm[t] = nn * factor;
    float mbind = g_P[t] * (1.f / 524288.f);        // /(B*H*N)
    float scale = mbind * factor * (1.f / 8192.f);  // mean_value = sumV/(B*H)
#pragma unroll 8
    for (int d = 0; d < 64; d++)
        out_key[t * 64 + d] = scale * g_sumV[t * 64 + d];
}

// ---------------- kernel 3: retrieve via HMMA ----------------
// grid 1024: h = bid>>4, bg = bid&15; each CTA does 8 b-values with 128 threads (4 warps).
// GEMM1: raw[m][d] = sum_n mkT[m][n] * q16[n][d]       (A = mkT [m][n], B = q16 [n][d] via ldmatrix.trans)
// GEMM2: out[n][d] = inv[d] * sum_m mv[n][m] * s16[m][d] (A = mv hi/lo [n][m], B = s16 [m][d] via ldmatrix.trans)
#define RP 72   // padded row length in halves (conflict-free ldmatrix)

__global__ void __launch_bounds__(128) k_retrieve(const float* __restrict__ q,
                                                  const float* __restrict__ mkey,
                                                  const float* __restrict__ mvalue,
                                                  const float* __restrict__ mnorm,
                                                  float* __restrict__ scores_out,
                                                  float* __restrict__ out_out) {
    __shared__ __half s_mkT[64 * RP];   // A1: [m][n]
    __shared__ __half s_mvhi[64 * RP];  // A2 hi: [n][m]
    __shared__ __half s_mvlo[64 * RP];  // A2 lo: [n][m]
    __shared__ __half s_q[64 * RP];     // B1: [n][d]
    __shared__ __half s_s[64 * RP];     // B2: [m][d]
    __shared__ float s_inv[64];

    int t = threadIdx.x, w = t >> 5, lane = t & 31, g = lane >> 2, tq = lane & 3;
    int h = blockIdx.x >> 4, bg = blockIdx.x & 15;

    if (t < 64) s_inv[t] = 1.0f / (mnorm[t] + 1e-6f);
    {
        const float* mk = mkey + ((unsigned)h << 12);
        const float* mv = mvalue + ((unsigned)h << 12);
        for (int i = t; i < 4096; i += 128) {
            int n = i >> 6, m = i & 63;
            s_mkT[m * RP + n] = __float2half_rn(mk[i]);
            float v = mv[i];
            __half hi = __float2half_rn(v);
            s_mvhi[n * RP + m] = hi;
            s_mvlo[n * RP + m] = __float2half_rn(v - __half2float(hi));
        }
    }
    __syncthreads();

    // preload A fragments (reused for all 8 b)
    int matv = lane >> 3, rr = lane & 7;
    int arow = w * 16 + rr + (matv & 1) * 8;
    int acolo = (matv >> 1) * 8;
    unsigned a1[4][4], ah[4][4], al[4][4];
#pragma unroll
    for (int ks = 0; ks < 4; ks++) {
        unsigned ad = sptr(&s_mkT[arow * RP + ks * 16 + acolo]);
        asm volatile("ldmatrix.sync.aligned.m8n8.x4.shared.b16 {%0,%1,%2,%3},[%4];"
                     : "=r"(a1[ks][0]), "=r"(a1[ks][1]), "=r"(a1[ks][2]), "=r"(a1[ks][3])
                     : "r"(ad));
        ad = sptr(&s_mvhi[arow * RP + ks * 16 + acolo]);
        asm volatile("ldmatrix.sync.aligned.m8n8.x4.shared.b16 {%0,%1,%2,%3},[%4];"
                     : "=r"(ah[ks][0]), "=r"(ah[ks][1]), "=r"(ah[ks][2]), "=r"(ah[ks][3])
                     : "r"(ad));
        ad = sptr(&s_mvlo[arow * RP + ks * 16 + acolo]);
        asm volatile("ldmatrix.sync.aligned.m8n8.x4.shared.b16 {%0,%1,%2,%3},[%4];"
                     : "=r"(al[ks][0]), "=r"(al[ks][1]), "=r"(al[ks][2]), "=r"(al[ks][3])
                     : "r"(ad));
    }
    int l16 = lane & 15;
    int brow = ((l16 >> 3) * 8 + (l16 & 7)) * RP;  // + ks*16*RP per k-step

    for (int j = 0; j < 8; j++) {
        int b = bg * 8 + j;
        unsigned base = ((unsigned)(b * 64 + h)) << 12;

        // load q -> s_q (f32 -> f16)
        {
            const float4* q4 = (const float4*)(q + base);
            for (int i = t; i < 1024; i += 128) {
                float4 v = q4[i];
                int n = i >> 4, d4 = (i & 15) << 2;
                *(__half2*)&s_q[n * RP + d4]     = __floats2half2_rn(v.x, v.y);
                *(__half2*)&s_q[n * RP + d4 + 2] = __floats2half2_rn(v.z, v.w);
            }
        }
        __syncthreads();

        // GEMM1 + scores epilogue
        float* sco = scores_out + base;
#pragma unroll
        for (int nt = 0; nt < 8; nt++) {
            float c0 = 0.f, c1 = 0.f, c2 = 0.f, c3 = 0.f;
#pragma unroll
            for (int ks = 0; ks < 4; ks++) {
                unsigned b0, b1;
                unsigned bad = sptr(&s_q[ks * 16 * RP + brow + nt * 8]);
                asm volatile("ldmatrix.sync.aligned.m8n8.x2.trans.shared.b16 {%0,%1},[%2];"
                             : "=r"(b0), "=r"(b1) : "r"(bad));
                asm volatile(
                    "mma.sync.aligned.m16n8k16.row.col.f32.f16.f16.f32 "
                    "{%0,%1,%2,%3},{%4,%5,%6,%7},{%8,%9},{%0,%1,%2,%3};"
                    : "+f"(c0), "+f"(c1), "+f"(c2), "+f"(c3)
                    : "r"(a1[ks][0]), "r"(a1[ks][1]), "r"(a1[ks][2]), "r"(a1[ks][3]),
                      "r"(b0), "r"(b1));
            }
            int m0 = w * 16 + g, d0 = nt * 8 + 2 * tq;
            __half h0 = __float2half_rn(c0), h1 = __float2half_rn(c1);
            __half h2 = __float2half_rn(c2), h3 = __float2half_rn(c3);
            *(__half2*)&s_s[m0 * RP + d0]       = __halves2half2(h0, h1);
            *(__half2*)&s_s[(m0 + 8) * RP + d0] = __halves2half2(h2, h3);
            float iv0 = s_inv[d0], iv1 = s_inv[d0 + 1];
            *(float2*)&sco[m0 * 64 + d0] =
                make_float2(__half2float(h0) * iv0, __half2float(h1) * iv1);
            *(float2*)&sco[(m0 + 8) * 64 + d0] =
                make_float2(__half2float(h2) * iv0, __half2float(h3) * iv1);
        }
        __syncthreads();

        // GEMM2 + output epilogue
        float* oo = out_out + base;
#pragma unroll
        for (int nt = 0; nt < 8; nt++) {
            float c0 = 0.f, c1 = 0.f, c2 = 0.f, c3 = 0.f;
#pragma unroll
            for (int ks = 0; ks < 4; ks++) {
                unsigned b0, b1;
                unsigned bad = sptr(&s_s[ks * 16 * RP + brow + nt * 8]);
                asm volatile("ldmatrix.sync.aligned.m8n8.x2.trans.shared.b16 {%0,%1},[%2];"
                             : "=r"(b0), "=r"(b1) : "r"(bad));
                asm volatile(
                    "mma.sync.aligned.m16n8k16.row.col.f32.f16.f16.f32 "
                    "{%0,%1,%2,%3},{%4,%5,%6,%7},{%8,%9},{%0,%1,%2,%3};"
                    : "+f"(c0), "+f"(c1), "+f"(c2), "+f"(c3)
                    : "r"(ah[ks][0]), "r"(ah[ks][1]), "r"(ah[ks][2]), "r"(ah[ks][3]),
                      "r"(b0), "r"(b1));
                asm volatile(
                    "mma.sync.aligned.m16n8k16.row.col.f32.f16.f16.f32 "
                    "{%0,%1,%2,%3},{%4,%5,%6,%7},{%8,%9},{%0,%1,%2,%3};"
                    : "+f"(c0), "+f"(c1), "+f"(c2), "+f"(c3)
                    : "r"(al[ks][0]), "r"(al[ks][1]), "r"(al[ks][2]), "r"(al[ks][3]),
                      "r"(b0), "r"(b1));
            }
            int n0 = w * 16 + g, d0 = nt * 8 + 2 * tq;
            float iv0 = s_inv[d0], iv1 = s_inv[d0 + 1];
            *(float2*)&oo[n0 * 64 + d0]       = make_float2(c0 * iv0, c1 * iv1);
            *(float2*)&oo[(n0 + 8) * 64 + d0] = make_float2(c2 * iv0, c3 * iv1);
        }
        // next iteration's q-load sync provides the s_s write/read fence
    }
}

extern "C" void kernel_launch(void* const* d_in, const int* in_sizes, int n_in,
                              void* d_out, int out_size) {
    const float* query  = (const float*)d_in[0];
    const float* key    = (const float*)d_in[1];
    const float* value  = (const float*)d_in[2];
    const float* mkey   = (const float*)d_in[3];
    const float* mnorm  = (const float*)d_in[4];
    const float* mvalue = (const float*)d_in[5];
    const float* comp   = (const float*)d_in[6];
    float* out = (float*)d_out;

    k_zero<<<16, 256>>>();
    k_update<<<512, 256>>>(key, value);
    k_stats<<<1, 64>>>(mnorm, comp, out + OFF_MKEY, out + OFF_MNORM);
    k_retrieve<<<1024, 128>>>(query, mkey, mvalue, mnorm, out + OFF_SCORES, out);
}